// round 4
// baseline (speedup 1.0000x reference)
#include <cuda_runtime.h>

// ---------------------------------------------------------------------------
// 2-layer GRU, B=256, T=24, D=2, N=512, H=128.  (R4: packed f32x2 FFMA2)
// Each CTA: 64 sequences, hidden state resident in SMEM (stored duplicated
// {h,h} per element so one LDS.64 yields a broadcast f32x2 operand).
// Weight LDS.128 yields gate-column pairs directly as f32x2 operands.
// Inner k: 3 LDS.128 + 4 LDS.64 + 24 FFMA2  (was 4 LDS.128 + 48 FFMA).
// ---------------------------------------------------------------------------

namespace {
constexpr int Bb      = 256;
constexpr int Tt      = 24;
constexpr int Dd      = 2;
constexpr int Nn      = 512;
constexpr int Hh      = 128;
constexpr int G3      = 384;     // 3*H
constexpr int SEQ     = 64;      // sequences per CTA
constexpr int THREADS = 512;
constexpr int CTAS    = Bb * (Nn / SEQ);  // 2048

// shared memory layout (float offsets)
constexpr int OFF_WS  = 0;                      // 32 x 384 weight staging chunk
constexpr int OFF_H0  = OFF_WS + 32 * G3;       // h0 dup: [128][64][2]
constexpr int OFF_H1  = OFF_H0 + Hh * SEQ * 2;  // h1 dup: [128][64][2]
constexpr int OFF_X   = OFF_H1 + Hh * SEQ * 2;  // xs [T][D][SEQ]
constexpr int OFF_WX0 = OFF_X  + Tt * Dd * SEQ; // Wx0 [2][384]
constexpr int OFF_BX0 = OFF_WX0 + Dd * G3;
constexpr int OFF_BH0 = OFF_BX0 + G3;
constexpr int OFF_BX1 = OFF_BH0 + G3;
constexpr int OFF_BH1 = OFF_BX1 + G3;
constexpr int SMEM_FLOATS = OFF_BH1 + G3;       // 50432 floats = 201728 bytes
}

using u64 = unsigned long long;

__device__ __forceinline__ void ffma2(u64& d, u64 a, u64 b) {
    // packed fp32x2 fused multiply-add (Blackwell): d = a*b + d, per 32-bit lane
    asm("fma.rn.f32x2 %0, %1, %2, %0;" : "+l"(d) : "l"(a), "l"(b));
}
__device__ __forceinline__ float2 unpk(u64 v) {
    float2 f;
    asm("mov.b64 {%0, %1}, %2;" : "=f"(f.x), "=f"(f.y) : "l"(v));
    return f;
}

__device__ __forceinline__ float sigm_f(float x) {
    return __fdividef(1.0f, 1.0f + __expf(-x));
}
__device__ __forceinline__ float tanh_f(float x) {
    float e = __expf(2.0f * x);
    return 1.0f - __fdividef(2.0f, e + 1.0f);
}

__global__ void __launch_bounds__(THREADS)
gru_fused_kernel(const float* __restrict__ x,
                 const float* __restrict__ Wx0, const float* __restrict__ Wh0,
                 const float* __restrict__ bx0, const float* __restrict__ bh0,
                 const float* __restrict__ Wx1, const float* __restrict__ Wh1,
                 const float* __restrict__ bx1, const float* __restrict__ bh1,
                 float* __restrict__ out)
{
    extern __shared__ float sm[];
    float* Ws   = sm + OFF_WS;
    float* h0d  = sm + OFF_H0;
    float* h1d  = sm + OFF_H1;
    float* xs   = sm + OFF_X;
    float* wx0s = sm + OFF_WX0;
    float* vbx0 = sm + OFF_BX0;
    float* vbh0 = sm + OFF_BH0;
    float* vbx1 = sm + OFF_BX1;
    float* vbh1 = sm + OFF_BH1;

    const int tid = threadIdx.x;
    const int b   = blockIdx.x >> 3;
    const int n0  = (blockIdx.x & 7) * SEQ;
    const int s0  = tid & 15;                 // base seq; owns s0 + 16*{0,1,2,3}
    const int g0  = (tid >> 4) * 4;           // 4 gate columns

    // ---- stage per-CTA constants ----
    for (int i = tid; i < Tt * Dd * SEQ; i += THREADS) {
        int t = i >> 7;
        int d = (i >> 6) & 1;
        int s = i & 63;
        xs[i] = x[((b * Tt + t) * Dd + d) * Nn + n0 + s];
    }
    for (int i = tid; i < Dd * G3; i += THREADS) wx0s[i] = Wx0[i];
    for (int i = tid; i < G3; i += THREADS) {
        vbx0[i] = bx0[i]; vbh0[i] = bh0[i];
        vbx1[i] = bx1[i]; vbh1[i] = bh1[i];
    }
    for (int i = tid; i < Hh * SEQ * 2; i += THREADS) { h0d[i] = 0.0f; h1d[i] = 0.0f; }

    #pragma unroll 1
    for (int t = 0; t < Tt; t++) {
        // ================= layer 0: acc = h0 @ Wh0 =================
        // pairs: [0..1]=r cols (g0..g0+3), [2..3]=z, [4..5]=n
        u64 acc2[4][6];
        #pragma unroll
        for (int s = 0; s < 4; s++)
            #pragma unroll
            for (int j = 0; j < 6; j++) acc2[s][j] = 0ULL;

        #pragma unroll 1
        for (int kc = 0; kc < 4; kc++) {
            __syncthreads();
            {
                const float4* src = reinterpret_cast<const float4*>(Wh0 + kc * 32 * G3);
                float4* dst = reinterpret_cast<float4*>(Ws);
                #pragma unroll
                for (int i = 0; i < (32 * G3 / 4) / THREADS; i++)  // 6
                    dst[tid + i * THREADS] = src[tid + i * THREADS];
            }
            __syncthreads();
            #pragma unroll 4
            for (int kk = 0; kk < 32; kk++) {
                const int k = kc * 32 + kk;
                const float* hb = &h0d[k * (SEQ * 2)];
                u64 h2[4];
                #pragma unroll
                for (int s = 0; s < 4; s++)
                    h2[s] = *reinterpret_cast<const u64*>(hb + (s0 + 16 * s) * 2);
                ulonglong2 wr = *reinterpret_cast<const ulonglong2*>(&Ws[kk * G3 + g0]);
                ulonglong2 wz = *reinterpret_cast<const ulonglong2*>(&Ws[kk * G3 + 128 + g0]);
                ulonglong2 wn = *reinterpret_cast<const ulonglong2*>(&Ws[kk * G3 + 256 + g0]);
                #pragma unroll
                for (int s = 0; s < 4; s++) {
                    ffma2(acc2[s][0], h2[s], wr.x);
                    ffma2(acc2[s][1], h2[s], wr.y);
                    ffma2(acc2[s][2], h2[s], wz.x);
                    ffma2(acc2[s][3], h2[s], wz.y);
                    ffma2(acc2[s][4], h2[s], wn.x);
                    ffma2(acc2[s][5], h2[s], wn.y);
                }
            }
        }
        __syncthreads();   // all GEMM reads of h0d done before epilogue writes

        // ---- layer-0 gate epilogue ----
        #pragma unroll
        for (int s = 0; s < 4; s++) {
            const int seq = s0 + 16 * s;
            const float x0v = xs[(t * Dd + 0) * SEQ + seq];
            const float x1v = xs[(t * Dd + 1) * SEQ + seq];
            float2 pr0 = unpk(acc2[s][0]), pr1 = unpk(acc2[s][1]);
            float2 pz0 = unpk(acc2[s][2]), pz1 = unpk(acc2[s][3]);
            float2 pn0 = unpk(acc2[s][4]), pn1 = unpk(acc2[s][5]);
            const float ar[4] = {pr0.x, pr0.y, pr1.x, pr1.y};
            const float az[4] = {pz0.x, pz0.y, pz1.x, pz1.y};
            const float an[4] = {pn0.x, pn0.y, pn1.x, pn1.y};
            #pragma unroll
            for (int j = 0; j < 4; j++) {
                const int g = g0 + j;
                float gir = fmaf(x1v, wx0s[G3 + g],       fmaf(x0v, wx0s[g],       vbx0[g]));
                float giz = fmaf(x1v, wx0s[G3 + 128 + g], fmaf(x0v, wx0s[128 + g], vbx0[128 + g]));
                float gin = fmaf(x1v, wx0s[G3 + 256 + g], fmaf(x0v, wx0s[256 + g], vbx0[256 + g]));
                float r  = sigm_f(ar[j] + vbh0[g]       + gir);
                float z  = sigm_f(az[j] + vbh0[128 + g] + giz);
                float hn = an[j] + vbh0[256 + g];
                float nn = tanh_f(gin + r * hn);
                float ho = h0d[(g * SEQ + seq) * 2];
                float hv = (1.0f - z) * nn + z * ho;
                *reinterpret_cast<float2*>(&h0d[(g * SEQ + seq) * 2]) = make_float2(hv, hv);
            }
        }
        __syncthreads();   // new h0 visible to layer-1 GEMM

        // ================= layer 1 =================
        // pairs: [0..1]=r, [2..3]=z, [4..5]=i_n (x-path), [6..7]=h_n (h-path)
        u64 a2[4][8];
        #pragma unroll
        for (int s = 0; s < 4; s++)
            #pragma unroll
            for (int j = 0; j < 8; j++) a2[s][j] = 0ULL;

        // x-path: h0_new @ Wx1
        #pragma unroll 1
        for (int kc = 0; kc < 4; kc++) {
            __syncthreads();
            {
                const float4* src = reinterpret_cast<const float4*>(Wx1 + kc * 32 * G3);
                float4* dst = reinterpret_cast<float4*>(Ws);
                #pragma unroll
                for (int i = 0; i < (32 * G3 / 4) / THREADS; i++)
                    dst[tid + i * THREADS] = src[tid + i * THREADS];
            }
            __syncthreads();
            #pragma unroll 4
            for (int kk = 0; kk < 32; kk++) {
                const int k = kc * 32 + kk;
                const float* hb = &h0d[k * (SEQ * 2)];
                u64 h2[4];
                #pragma unroll
                for (int s = 0; s < 4; s++)
                    h2[s] = *reinterpret_cast<const u64*>(hb + (s0 + 16 * s) * 2);
                ulonglong2 wr = *reinterpret_cast<const ulonglong2*>(&Ws[kk * G3 + g0]);
                ulonglong2 wz = *reinterpret_cast<const ulonglong2*>(&Ws[kk * G3 + 128 + g0]);
                ulonglong2 wn = *reinterpret_cast<const ulonglong2*>(&Ws[kk * G3 + 256 + g0]);
                #pragma unroll
                for (int s = 0; s < 4; s++) {
                    ffma2(a2[s][0], h2[s], wr.x);
                    ffma2(a2[s][1], h2[s], wr.y);
                    ffma2(a2[s][2], h2[s], wz.x);
                    ffma2(a2[s][3], h2[s], wz.y);
                    ffma2(a2[s][4], h2[s], wn.x);
                    ffma2(a2[s][5], h2[s], wn.y);
                }
            }
        }
        // h-path: h1 @ Wh1
        #pragma unroll 1
        for (int kc = 0; kc < 4; kc++) {
            __syncthreads();
            {
                const float4* src = reinterpret_cast<const float4*>(Wh1 + kc * 32 * G3);
                float4* dst = reinterpret_cast<float4*>(Ws);
                #pragma unroll
                for (int i = 0; i < (32 * G3 / 4) / THREADS; i++)
                    dst[tid + i * THREADS] = src[tid + i * THREADS];
            }
            __syncthreads();
            #pragma unroll 4
            for (int kk = 0; kk < 32; kk++) {
                const int k = kc * 32 + kk;
                const float* hb = &h1d[k * (SEQ * 2)];
                u64 h2[4];
                #pragma unroll
                for (int s = 0; s < 4; s++)
                    h2[s] = *reinterpret_cast<const u64*>(hb + (s0 + 16 * s) * 2);
                ulonglong2 wr = *reinterpret_cast<const ulonglong2*>(&Ws[kk * G3 + g0]);
                ulonglong2 wz = *reinterpret_cast<const ulonglong2*>(&Ws[kk * G3 + 128 + g0]);
                ulonglong2 wn = *reinterpret_cast<const ulonglong2*>(&Ws[kk * G3 + 256 + g0]);
                #pragma unroll
                for (int s = 0; s < 4; s++) {
                    ffma2(a2[s][0], h2[s], wr.x);
                    ffma2(a2[s][1], h2[s], wr.y);
                    ffma2(a2[s][2], h2[s], wz.x);
                    ffma2(a2[s][3], h2[s], wz.y);
                    ffma2(a2[s][6], h2[s], wn.x);
                    ffma2(a2[s][7], h2[s], wn.y);
                }
            }
        }
        __syncthreads();   // all GEMM reads of h1d done before epilogue writes

        // ---- layer-1 gate epilogue ----
        #pragma unroll
        for (int s = 0; s < 4; s++) {
            const int seq = s0 + 16 * s;
            float2 pr0 = unpk(a2[s][0]), pr1 = unpk(a2[s][1]);
            float2 pz0 = unpk(a2[s][2]), pz1 = unpk(a2[s][3]);
            float2 pi0 = unpk(a2[s][4]), pi1 = unpk(a2[s][5]);
            float2 ph0 = unpk(a2[s][6]), ph1 = unpk(a2[s][7]);
            const float ar[4] = {pr0.x, pr0.y, pr1.x, pr1.y};
            const float az[4] = {pz0.x, pz0.y, pz1.x, pz1.y};
            const float ai[4] = {pi0.x, pi0.y, pi1.x, pi1.y};
            const float ah[4] = {ph0.x, ph0.y, ph1.x, ph1.y};
            #pragma unroll
            for (int j = 0; j < 4; j++) {
                const int g = g0 + j;
                float r   = sigm_f(ar[j] + vbx1[g]       + vbh1[g]);
                float z   = sigm_f(az[j] + vbx1[128 + g] + vbh1[128 + g]);
                float in_ = ai[j] + vbx1[256 + g];
                float hn  = ah[j] + vbh1[256 + g];
                float nn  = tanh_f(in_ + r * hn);
                float ho  = h1d[(g * SEQ + seq) * 2];
                float hv  = (1.0f - z) * nn + z * ho;
                *reinterpret_cast<float2*>(&h1d[(g * SEQ + seq) * 2]) = make_float2(hv, hv);
            }
        }
        __syncthreads();
    }

    // ---- write final hidden states: out[2][B][H][N] ----
    for (int i = tid; i < 2 * Hh * SEQ; i += THREADS) {
        int l   = i >> 13;
        int rem = i & 8191;
        int g   = rem >> 6;
        int s   = rem & 63;
        float v = (l ? h1d : h0d)[(g * SEQ + s) * 2];
        out[((l * Bb + b) * Hh + g) * Nn + n0 + s] = v;
    }
}

extern "C" void kernel_launch(void* const* d_in, const int* in_sizes, int n_in,
                              void* d_out, int out_size) {
    (void)in_sizes; (void)n_in; (void)out_size;
    const float* x   = (const float*)d_in[0];
    const float* Wx0 = (const float*)d_in[1];
    const float* Wh0 = (const float*)d_in[2];
    const float* bx0 = (const float*)d_in[3];
    const float* bh0 = (const float*)d_in[4];
    const float* Wx1 = (const float*)d_in[5];
    const float* Wh1 = (const float*)d_in[6];
    const float* bx1 = (const float*)d_in[7];
    const float* bh1 = (const float*)d_in[8];
    float* out = (float*)d_out;

    const size_t smem_bytes = SMEM_FLOATS * sizeof(float);  // 201728
    cudaFuncSetAttribute(gru_fused_kernel,
                         cudaFuncAttributeMaxDynamicSharedMemorySize,
                         (int)smem_bytes);

    gru_fused_kernel<<<CTAS, THREADS, smem_bytes>>>(
        x, Wx0, Wh0, bx0, bh0, Wx1, Wh1, bx1, bh1, out);
}